// round 2
// baseline (speedup 1.0000x reference)
#include <cuda_runtime.h>
#include <math.h>

#define Nn     30000
#define Ee     300000
#define ETOT   330000      // E + N self loops
#define Gg     128
#define INDIM  128
#define HIDC   64
#define NHEAD  4
#define CCH    256         // HIDC*NHEAD
#define NCLS   10
#define EPSBN  1e-5f
#define SLOPE  0.2f
#define RPB    64          // rows per block for BN stats

// ---------------- scratch (allocation-free: device globals) ----------------
__device__ float g_H  [Nn * CCH];
__device__ float g_XL [Nn * CCH];
__device__ float g_XR [Nn * CCH];
__device__ float g_AGG[Nn * CCH];
__device__ float g_sc [ETOT * NHEAD];
__device__ float g_p  [ETOT * NHEAD];
__device__ float g_m  [Nn * NHEAD];
__device__ float g_s  [Nn * NHEAD];
__device__ float g_bnsum[CCH];
__device__ float g_bnsq [CCH];
__device__ float g_pool[Gg * HIDC];
__device__ float g_cnt [Gg];

// ---------------- helpers ----------------
__device__ __forceinline__ void atomicMaxFloat(float* addr, float v) {
    // init is -inf (0xff800000). Works for mixed signs:
    if (v >= 0.f) atomicMax((int*)addr, __float_as_int(v));
    else          atomicMin((unsigned int*)addr, __float_as_uint(v));
}

// ---------------- GEMM: C[M,256] = A[M,K] * B[K,256], fp32 ----------------
// 128x128 tile, BK=8, 256 threads, 8x8 per thread.
__global__ void sgemm(const float* __restrict__ A, const float* __restrict__ B,
                      float* __restrict__ C, int M, int K) {
    __shared__ float As[8][128];
    __shared__ float Bs[8][128];
    const int tid = threadIdx.x;
    const int bm = blockIdx.x * 128;
    const int bn = blockIdx.y * 128;
    const int tx = tid & 15, ty = tid >> 4;
    const int arow = tid >> 1, akk = (tid & 1) * 4;
    const int bkk = tid >> 5,  bcol = (tid & 31) * 4;
    float acc[8][8];
#pragma unroll
    for (int i = 0; i < 8; i++)
#pragma unroll
        for (int j = 0; j < 8; j++) acc[i][j] = 0.f;

    const int arowg = bm + arow;
    const bool aok = arowg < M;

    for (int k0 = 0; k0 < K; k0 += 8) {
        float4 av = make_float4(0.f, 0.f, 0.f, 0.f);
        if (aok) av = *(const float4*)(A + (size_t)arowg * K + k0 + akk);
        As[akk + 0][arow] = av.x;
        As[akk + 1][arow] = av.y;
        As[akk + 2][arow] = av.z;
        As[akk + 3][arow] = av.w;
        *(float4*)&Bs[bkk][bcol] =
            *(const float4*)(B + (size_t)(k0 + bkk) * CCH + bn + bcol);
        __syncthreads();
#pragma unroll
        for (int kk = 0; kk < 8; kk++) {
            float4 a0 = *(float4*)&As[kk][ty * 4];
            float4 a1 = *(float4*)&As[kk][64 + ty * 4];
            float4 b0 = *(float4*)&Bs[kk][tx * 4];
            float4 b1 = *(float4*)&Bs[kk][64 + tx * 4];
            float ar[8] = {a0.x, a0.y, a0.z, a0.w, a1.x, a1.y, a1.z, a1.w};
            float br[8] = {b0.x, b0.y, b0.z, b0.w, b1.x, b1.y, b1.z, b1.w};
#pragma unroll
            for (int i = 0; i < 8; i++)
#pragma unroll
                for (int j = 0; j < 8; j++)
                    acc[i][j] = fmaf(ar[i], br[j], acc[i][j]);
        }
        __syncthreads();
    }
#pragma unroll
    for (int i = 0; i < 8; i++) {
        int row = bm + ((i < 4) ? (ty * 4 + i) : (64 + ty * 4 + i - 4));
        if (row < M) {
            float4 s0 = make_float4(acc[i][0], acc[i][1], acc[i][2], acc[i][3]);
            float4 s1 = make_float4(acc[i][4], acc[i][5], acc[i][6], acc[i][7]);
            *(float4*)(C + (size_t)row * CCH + bn + tx * 4) = s0;
            *(float4*)(C + (size_t)row * CCH + bn + 64 + tx * 4) = s1;
        }
    }
}

// ---------------- per-layer init ----------------
__global__ void init_layer() {
    int i = blockIdx.x * blockDim.x + threadIdx.x;
    if (i < Nn * CCH) g_AGG[i] = 0.f;
    if (i < Nn * NHEAD) { g_m[i] = __int_as_float(0xff800000); g_s[i] = 0.f; }
    if (i < CCH) { g_bnsum[i] = 0.f; g_bnsq[i] = 0.f; }
}

// ---------------- edge scores: warp per edge ----------------
// lane = 8*h + j ; each lane handles 8 channels of head h.
__global__ void k_scores(const int* __restrict__ ei, const float* __restrict__ att) {
    int gw = (blockIdx.x * blockDim.x + threadIdx.x) >> 5;
    if (gw >= ETOT) return;
    int lane = threadIdx.x & 31;
    int h = lane >> 3, j = lane & 7;
    int src, dst;
    if (gw < Ee) { src = ei[gw]; dst = ei[Ee + gw]; }
    else         { src = gw - Ee; dst = src; }
    int off = h * HIDC + j * 8;
    const float4* xl = (const float4*)(g_XL + (size_t)src * CCH + off);
    const float4* xr = (const float4*)(g_XR + (size_t)dst * CCH + off);
    const float4* at = (const float4*)(att + off);
    float4 a0 = xl[0], a1 = xl[1];
    float4 r0 = xr[0], r1 = xr[1];
    float4 t0 = at[0], t1 = at[1];
    float sum = 0.f, z;
    z = a0.x + r0.x; z = z > 0.f ? z : SLOPE * z; sum = fmaf(t0.x, z, sum);
    z = a0.y + r0.y; z = z > 0.f ? z : SLOPE * z; sum = fmaf(t0.y, z, sum);
    z = a0.z + r0.z; z = z > 0.f ? z : SLOPE * z; sum = fmaf(t0.z, z, sum);
    z = a0.w + r0.w; z = z > 0.f ? z : SLOPE * z; sum = fmaf(t0.w, z, sum);
    z = a1.x + r1.x; z = z > 0.f ? z : SLOPE * z; sum = fmaf(t1.x, z, sum);
    z = a1.y + r1.y; z = z > 0.f ? z : SLOPE * z; sum = fmaf(t1.y, z, sum);
    z = a1.z + r1.z; z = z > 0.f ? z : SLOPE * z; sum = fmaf(t1.z, z, sum);
    z = a1.w + r1.w; z = z > 0.f ? z : SLOPE * z; sum = fmaf(t1.w, z, sum);
    sum += __shfl_down_sync(0xffffffffu, sum, 4);
    sum += __shfl_down_sync(0xffffffffu, sum, 2);
    sum += __shfl_down_sync(0xffffffffu, sum, 1);
    if (j == 0) {
        g_sc[gw * NHEAD + h] = sum;
        atomicMaxFloat(&g_m[dst * NHEAD + h], sum);
    }
}

// ---------------- exp + segment sum ----------------
__global__ void k_expsum(const int* __restrict__ ei) {
    int i = blockIdx.x * blockDim.x + threadIdx.x;
    if (i >= ETOT * NHEAD) return;
    int e = i >> 2, h = i & 3;
    int dst = (e < Ee) ? ei[Ee + e] : e - Ee;
    float p = expf(g_sc[i] - g_m[dst * NHEAD + h]);
    g_p[i] = p;
    atomicAdd(&g_s[dst * NHEAD + h], p);
}

// ---------------- weighted aggregation: warp per edge ----------------
__global__ void k_aggregate(const int* __restrict__ ei) {
    int gw = (blockIdx.x * blockDim.x + threadIdx.x) >> 5;
    if (gw >= ETOT) return;
    int lane = threadIdx.x & 31;
    int h = lane >> 3, j = lane & 7;
    int src, dst;
    if (gw < Ee) { src = ei[gw]; dst = ei[Ee + gw]; }
    else         { src = gw - Ee; dst = src; }
    float alpha = g_p[gw * NHEAD + h] / g_s[dst * NHEAD + h];
    int off = h * HIDC + j * 8;
    const float4* xl = (const float4*)(g_XL + (size_t)src * CCH + off);
    float4 v0 = xl[0], v1 = xl[1];
    float* o = g_AGG + (size_t)dst * CCH + off;
    atomicAdd(o + 0, alpha * v0.x);
    atomicAdd(o + 1, alpha * v0.y);
    atomicAdd(o + 2, alpha * v0.z);
    atomicAdd(o + 3, alpha * v0.w);
    atomicAdd(o + 4, alpha * v1.x);
    atomicAdd(o + 5, alpha * v1.y);
    atomicAdd(o + 6, alpha * v1.z);
    atomicAdd(o + 7, alpha * v1.w);
}

// ---------------- bias + BN statistics (concat layers, C=256) ----------------
__global__ void k_bias_bnstats(const float* __restrict__ b) {
    int c = threadIdx.x;                 // 256 = channel
    int r0 = blockIdx.x * RPB;
    int rend = min(r0 + RPB, Nn);
    float bc = b[c];
    float s = 0.f, s2 = 0.f;
    for (int r = r0; r < rend; r++) {
        float v = g_AGG[(size_t)r * CCH + c] + bc;
        g_H[(size_t)r * CCH + c] = v;
        s += v; s2 += v * v;
    }
    atomicAdd(&g_bnsum[c], s);
    atomicAdd(&g_bnsq[c], s2);
}

// ---------------- head-mean + bias + BN stats (last layer, C=64) ----------------
__global__ void k_meanheads(const float* __restrict__ b) {
    int t = threadIdx.x;                 // 256
    int c = t & 63, sub = t >> 6;        // 4 row-lanes
    int rbase = blockIdx.x * RPB;
    int rend = min(rbase + RPB, Nn);
    float bc = b[c];
    float s = 0.f, s2 = 0.f;
    for (int r = rbase + sub; r < rend; r += 4) {
        const float* row = g_AGG + (size_t)r * CCH;
        float v = 0.25f * (row[c] + row[64 + c] + row[128 + c] + row[192 + c]) + bc;
        g_H[(size_t)r * HIDC + c] = v;
        s += v; s2 += v * v;
    }
    atomicAdd(&g_bnsum[c], s);
    atomicAdd(&g_bnsq[c], s2);
}

// ---------------- BN normalize + ELU ----------------
__global__ void k_bnapply(const float* __restrict__ gam, const float* __restrict__ bet,
                          int Ctot) {
    int i = blockIdx.x * blockDim.x + threadIdx.x;
    if (i >= Nn * Ctot) return;
    int c = i % Ctot;
    float mu = g_bnsum[c] * (1.f / Nn);
    float var = g_bnsq[c] * (1.f / Nn) - mu * mu;
    float v = gam[c] * (g_H[i] - mu) * rsqrtf(var + EPSBN) + bet[c];
    g_H[i] = v > 0.f ? v : expm1f(v);
}

// ---------------- pooling ----------------
__global__ void k_pool_init() {
    int i = blockIdx.x * blockDim.x + threadIdx.x;
    if (i < Gg * HIDC) g_pool[i] = 0.f;
    if (i < Gg) g_cnt[i] = 0.f;
}

__global__ void k_pool(const int* __restrict__ batch) {
    int i = blockIdx.x * blockDim.x + threadIdx.x;
    if (i >= Nn * HIDC) return;
    int n = i >> 6, c = i & 63;
    int g = batch[n];
    atomicAdd(&g_pool[g * HIDC + c], g_H[i]);
    if (c == 0) atomicAdd(&g_cnt[g], 1.f);
}

// ---------------- MLP head: one block per graph ----------------
__global__ void k_head(const float* __restrict__ fc1w, const float* __restrict__ fc1b,
                       const float* __restrict__ fc2w, const float* __restrict__ fc2b,
                       float* __restrict__ out) {
    __shared__ float p[64], q[64];
    int g = blockIdx.x, c = threadIdx.x;
    float cnt = fmaxf(g_cnt[g], 1.f);
    p[c] = g_pool[g * HIDC + c] / cnt;
    __syncthreads();
    float a = fc1b[c];
#pragma unroll 8
    for (int k = 0; k < 64; k++) a = fmaf(p[k], fc1w[k * 64 + c], a);
    q[c] = fmaxf(a, 0.f);
    __syncthreads();
    if (c < NCLS) {
        float o = fc2b[c];
#pragma unroll 8
        for (int k = 0; k < 64; k++) o = fmaf(q[k], fc2w[k * NCLS + c], o);
        out[g * NCLS + c] = o;
    }
}

// ---------------- launch ----------------
extern "C" void kernel_launch(void* const* d_in, const int* in_sizes, int n_in,
                              void* d_out, int out_size) {
    const float* x   = (const float*)d_in[0];
    const int* ei    = (const int*)d_in[1];
    const int* batch = (const int*)d_in[2];

    float *pH, *pXL, *pXR;
    cudaGetSymbolAddress((void**)&pH,  g_H);
    cudaGetSymbolAddress((void**)&pXL, g_XL);
    cudaGetSymbolAddress((void**)&pXR, g_XR);

    dim3 ggrid((Nn + 127) / 128, 2);
    int edgeWarpBlocks = (ETOT + 7) / 8;          // 256 thr = 8 warps/block

    for (int i = 0; i < 4; i++) {
        int base = 3 + 6 * i;
        const float* Wl  = (const float*)d_in[base + 0];
        const float* Wr  = (const float*)d_in[base + 1];
        const float* att = (const float*)d_in[base + 2];
        const float* b   = (const float*)d_in[base + 3];
        const float* gam = (const float*)d_in[base + 4];
        const float* bet = (const float*)d_in[base + 5];
        const float* A = (i == 0) ? x : pH;
        int K = (i == 0) ? INDIM : CCH;

        sgemm<<<ggrid, 256>>>(A, Wl, pXL, Nn, K);
        sgemm<<<ggrid, 256>>>(A, Wr, pXR, Nn, K);
        init_layer<<<(Nn * CCH + 255) / 256, 256>>>();
        k_scores<<<edgeWarpBlocks, 256>>>(ei, att);
        k_expsum<<<(ETOT * NHEAD + 255) / 256, 256>>>(ei);
        k_aggregate<<<edgeWarpBlocks, 256>>>(ei);
        if (i < 3) k_bias_bnstats<<<(Nn + RPB - 1) / RPB, 256>>>(b);
        else       k_meanheads<<<(Nn + RPB - 1) / RPB, 256>>>(b);
        int Ctot = (i < 3) ? CCH : HIDC;
        k_bnapply<<<(Nn * Ctot + 255) / 256, 256>>>(gam, bet, Ctot);
    }

    k_pool_init<<<(Gg * HIDC + 255) / 256, 256>>>();
    k_pool<<<(Nn * HIDC + 255) / 256, 256>>>(batch);
    k_head<<<Gg, 64>>>((const float*)d_in[27], (const float*)d_in[28],
                       (const float*)d_in[29], (const float*)d_in[30],
                       (float*)d_out);
}

// round 6
// speedup vs baseline: 2.3401x; 2.3401x over previous
#include <cuda_runtime.h>
#include <math.h>
#include <cstdint>

#define Nn     30000
#define Ee     300000
#define ETOT   330000
#define Gg     128
#define INDIM  128
#define HIDC   64
#define NHEAD  4
#define CCH    256
#define NCLS   10
#define EPSBN  1e-5f
#define SLOPE  0.2f
#define RPB    64

// ---------------- scratch ----------------
__device__ float g_H  [Nn * CCH];
__device__ float g_XL [Nn * CCH];
__device__ float g_XR [Nn * CCH];
__device__ int   g_deg [Nn];
__device__ int   g_offs[Nn + 1];
__device__ int   g_cur [Nn];
__device__ int   g_esrc[ETOT];
__device__ float g_bnsum[CCH];
__device__ float g_bnsq [CCH];
__device__ float g_pool[Gg * HIDC];
__device__ float g_cnt [Gg];

// ================= mma.sync tf32 helpers (sm_80+ portable) =================
__device__ __forceinline__ uint32_t f2tf(float f) {
    uint32_t r;
    asm("cvt.rna.tf32.f32 %0, %1;" : "=r"(r) : "f"(f));
    return r;
}
__device__ __forceinline__ void mma_tf32(float* d, const uint32_t* a, const uint32_t* b) {
    asm volatile(
        "mma.sync.aligned.m16n8k8.row.col.f32.tf32.tf32.f32 "
        "{%0,%1,%2,%3}, {%4,%5,%6,%7}, {%8,%9}, {%0,%1,%2,%3};"
        : "+f"(d[0]), "+f"(d[1]), "+f"(d[2]), "+f"(d[3])
        : "r"(a[0]), "r"(a[1]), "r"(a[2]), "r"(a[3]), "r"(b[0]), "r"(b[1]));
}

// ================= GEMM: C[M,256] = A[M,K] * B[K,256]  (3xTF32 split) =======
// 128x128 block tile, BK=32, 256 threads = 8 warps (2m x 4n), warp tile 64x32.
#define SA_STRIDE 36    // 4 mod 32 -> A-frag reads conflict-free
#define SB_STRIDE 136   // 8 mod 32 -> B-frag reads conflict-free
__global__ void __launch_bounds__(256) sgemm_mma(const float* __restrict__ A,
                                                 const float* __restrict__ B,
                                                 float* __restrict__ C, int M, int K) {
    __shared__ float sA[128 * SA_STRIDE];
    __shared__ float sB[32 * SB_STRIDE];
    const int tid = threadIdx.x;
    const int lane = tid & 31, wid = tid >> 5;
    const int wm = wid & 1, wn = wid >> 1;
    const int bm = blockIdx.x * 128, n0 = blockIdx.y * 128;
    const int r0 = lane >> 2, c0 = lane & 3;

    float d[4][4][4];
#pragma unroll
    for (int mt = 0; mt < 4; mt++)
#pragma unroll
        for (int nt = 0; nt < 4; nt++)
#pragma unroll
            for (int q = 0; q < 4; q++) d[mt][nt][q] = 0.f;

    const int arow = tid >> 1, acol = (tid & 1) * 16;
    const int brow = tid >> 3, bcol = (tid & 7) * 16;
    const bool aok = (bm + arow) < M;
    const float* Arow = A + (size_t)(bm + arow) * K;

    for (int k0 = 0; k0 < K; k0 += 32) {
#pragma unroll
        for (int i = 0; i < 4; i++) {
            float4 v = make_float4(0.f, 0.f, 0.f, 0.f);
            if (aok) v = *(const float4*)(Arow + k0 + acol + i * 4);
            *(float4*)(sA + arow * SA_STRIDE + acol + i * 4) = v;
        }
#pragma unroll
        for (int i = 0; i < 4; i++) {
            float4 v = *(const float4*)(B + (size_t)(k0 + brow) * CCH + n0 + bcol + i * 4);
            *(float4*)(sB + brow * SB_STRIDE + bcol + i * 4) = v;
        }
        __syncthreads();

#pragma unroll
        for (int ks = 0; ks < 4; ks++) {
            const int k = ks * 8;
            uint32_t ah[4][4], al[4][4], bh[4][2], bl[4][2];
#pragma unroll
            for (int mt = 0; mt < 4; mt++) {
                const int rm = wm * 64 + mt * 16;
                float f[4];
                f[0] = sA[(rm + r0) * SA_STRIDE + k + c0];
                f[1] = sA[(rm + r0 + 8) * SA_STRIDE + k + c0];
                f[2] = sA[(rm + r0) * SA_STRIDE + k + c0 + 4];
                f[3] = sA[(rm + r0 + 8) * SA_STRIDE + k + c0 + 4];
#pragma unroll
                for (int q = 0; q < 4; q++) {
                    uint32_t h = f2tf(f[q]);
                    ah[mt][q] = h;
                    al[mt][q] = f2tf(f[q] - __uint_as_float(h));
                }
            }
#pragma unroll
            for (int nt = 0; nt < 4; nt++) {
                const int cn = wn * 32 + nt * 8 + r0;
                float g[2];
                g[0] = sB[(k + c0) * SB_STRIDE + cn];
                g[1] = sB[(k + 4 + c0) * SB_STRIDE + cn];
#pragma unroll
                for (int q = 0; q < 2; q++) {
                    uint32_t h = f2tf(g[q]);
                    bh[nt][q] = h;
                    bl[nt][q] = f2tf(g[q] - __uint_as_float(h));
                }
            }
#pragma unroll
            for (int mt = 0; mt < 4; mt++)
#pragma unroll
                for (int nt = 0; nt < 4; nt++) {
                    mma_tf32(d[mt][nt], ah[mt], bh[nt]);
                    mma_tf32(d[mt][nt], ah[mt], bl[nt]);
                    mma_tf32(d[mt][nt], al[mt], bh[nt]);
                }
        }
        __syncthreads();
    }

    // epilogue
#pragma unroll
    for (int mt = 0; mt < 4; mt++) {
        const int row = bm + wm * 64 + mt * 16 + r0;
#pragma unroll
        for (int nt = 0; nt < 4; nt++) {
            const int col = n0 + wn * 32 + nt * 8 + c0 * 2;
            if (row < M)
                *(float2*)(C + (size_t)row * CCH + col) = make_float2(d[mt][nt][0], d[mt][nt][1]);
            if (row + 8 < M)
                *(float2*)(C + (size_t)(row + 8) * CCH + col) = make_float2(d[mt][nt][2], d[mt][nt][3]);
        }
    }
}

// ================= CSR build =================
__global__ void k_deg_zero() {
    int i = blockIdx.x * blockDim.x + threadIdx.x;
    if (i < Nn) g_deg[i] = 0;
}
__global__ void k_deg(const int* __restrict__ ei) {
    int i = blockIdx.x * blockDim.x + threadIdx.x;
    if (i >= ETOT) return;
    int dst = (i < Ee) ? ei[Ee + i] : i - Ee;
    atomicAdd(&g_deg[dst], 1);
}
__global__ void k_scan() {   // single block, 1024 threads
    __shared__ int sm[1024];
    int tid = threadIdx.x;
    int run = 0;
    for (int base = 0; base < Nn; base += 1024) {
        int i = base + tid;
        int v = (i < Nn) ? g_deg[i] : 0;
        sm[tid] = v;
        __syncthreads();
        for (int st = 1; st < 1024; st <<= 1) {
            int t = (tid >= st) ? sm[tid - st] : 0;
            __syncthreads();
            sm[tid] += t;
            __syncthreads();
        }
        if (i < Nn) {
            g_offs[i + 1] = run + sm[tid];
            g_cur[i]      = run + sm[tid] - v;
        }
        if (base == 0 && tid == 0) g_offs[0] = 0;
        run += sm[1023];
        __syncthreads();
    }
}
__global__ void k_fill(const int* __restrict__ ei) {
    int i = blockIdx.x * blockDim.x + threadIdx.x;
    if (i >= ETOT) return;
    int src, dst;
    if (i < Ee) { src = ei[i]; dst = ei[Ee + i]; }
    else        { src = i - Ee; dst = src; }
    int pos = atomicAdd(&g_cur[dst], 1);
    g_esrc[pos] = src;
}

// ================= fused edge phase: warp per dst, online softmax =================
__global__ void k_edge(const float* __restrict__ att, const float* __restrict__ b,
                       int concat) {
    int dst = (blockIdx.x * blockDim.x + threadIdx.x) >> 5;
    if (dst >= Nn) return;
    int lane = threadIdx.x & 31;
    int h = lane >> 3, j = lane & 7;
    int off = h * HIDC + j * 8;

    const float4* xr = (const float4*)(g_XR + (size_t)dst * CCH + off);
    const float4* at = (const float4*)(att + off);
    float4 r0 = xr[0], r1 = xr[1];
    float4 t0 = at[0], t1 = at[1];
    float r[8] = {r0.x, r0.y, r0.z, r0.w, r1.x, r1.y, r1.z, r1.w};
    float t[8] = {t0.x, t0.y, t0.z, t0.w, t1.x, t1.y, t1.z, t1.w};

    float acc[8] = {0.f, 0.f, 0.f, 0.f, 0.f, 0.f, 0.f, 0.f};
    float m = -3.0e38f;
    float s = 0.f;

    int beg = g_offs[dst], end = g_offs[dst + 1];
    for (int p = beg; p < end; p++) {
        int src = g_esrc[p];
        const float4* xl = (const float4*)(g_XL + (size_t)src * CCH + off);
        float4 a0 = xl[0], a1 = xl[1];
        float a[8] = {a0.x, a0.y, a0.z, a0.w, a1.x, a1.y, a1.z, a1.w};
        float sc = 0.f;
#pragma unroll
        for (int k = 0; k < 8; k++) {
            float z = a[k] + r[k];
            z = z > 0.f ? z : SLOPE * z;
            sc = fmaf(t[k], z, sc);
        }
        sc += __shfl_xor_sync(0xffffffffu, sc, 1);
        sc += __shfl_xor_sync(0xffffffffu, sc, 2);
        sc += __shfl_xor_sync(0xffffffffu, sc, 4);
        if (sc > m) {
            float scale = expf(m - sc);   // first edge: 0
            m = sc;
            s = fmaf(s, scale, 1.f);
#pragma unroll
            for (int k = 0; k < 8; k++) acc[k] = fmaf(acc[k], scale, a[k]);
        } else {
            float pe = expf(sc - m);
            s += pe;
#pragma unroll
            for (int k = 0; k < 8; k++) acc[k] = fmaf(pe, a[k], acc[k]);
        }
    }
    float inv = 1.f / s;
    if (concat) {
        float* o = g_H + (size_t)dst * CCH + off;
#pragma unroll
        for (int k = 0; k < 8; k++) o[k] = fmaf(acc[k], inv, b[off + k]);
    } else {
        float v[8];
#pragma unroll
        for (int k = 0; k < 8; k++) {
            v[k] = acc[k] * inv;
            v[k] += __shfl_xor_sync(0xffffffffu, v[k], 8);
            v[k] += __shfl_xor_sync(0xffffffffu, v[k], 16);
        }
        if (h == 0) {
            float* o = g_H + (size_t)dst * HIDC + j * 8;
#pragma unroll
            for (int k = 0; k < 8; k++) o[k] = fmaf(0.25f, v[k], b[j * 8 + k]);
        }
    }
}

// ================= BN =================
__global__ void k_init_bn() {
    int i = threadIdx.x;
    g_bnsum[i] = 0.f;
    g_bnsq[i] = 0.f;
}
__global__ void k_bnstats(int Ctot) {
    int tid = threadIdx.x;                 // 256
    int c = tid % Ctot, sub = tid / Ctot, nsub = 256 / Ctot;
    int r0 = blockIdx.x * RPB;
    int rend = min(r0 + RPB, Nn);
    float s = 0.f, s2 = 0.f;
    for (int r = r0 + sub; r < rend; r += nsub) {
        float v = g_H[(size_t)r * Ctot + c];
        s += v;
        s2 += v * v;
    }
    atomicAdd(&g_bnsum[c], s);
    atomicAdd(&g_bnsq[c], s2);
}
__global__ void k_bnapply(const float* __restrict__ gam, const float* __restrict__ bet,
                          int Ctot) {
    int i = blockIdx.x * blockDim.x + threadIdx.x;
    if (i >= Nn * Ctot) return;
    int c = i % Ctot;
    float mu = g_bnsum[c] * (1.f / Nn);
    float var = g_bnsq[c] * (1.f / Nn) - mu * mu;
    float v = gam[c] * (g_H[i] - mu) * rsqrtf(var + EPSBN) + bet[c];
    g_H[i] = v > 0.f ? v : expm1f(v);
}

// ================= pooling + head =================
__global__ void k_pool_init() {
    int i = blockIdx.x * blockDim.x + threadIdx.x;
    if (i < Gg * HIDC) g_pool[i] = 0.f;
    if (i < Gg) g_cnt[i] = 0.f;
}
__global__ void k_pool(const int* __restrict__ batch) {
    int i = blockIdx.x * blockDim.x + threadIdx.x;
    if (i >= Nn * HIDC) return;
    int n = i >> 6, c = i & 63;
    int g = batch[n];
    atomicAdd(&g_pool[g * HIDC + c], g_H[i]);
    if (c == 0) atomicAdd(&g_cnt[g], 1.f);
}
__global__ void k_head(const float* __restrict__ fc1w, const float* __restrict__ fc1b,
                       const float* __restrict__ fc2w, const float* __restrict__ fc2b,
                       float* __restrict__ out) {
    __shared__ float p[64], q[64];
    int g = blockIdx.x, c = threadIdx.x;
    float cnt = fmaxf(g_cnt[g], 1.f);
    p[c] = g_pool[g * HIDC + c] / cnt;
    __syncthreads();
    float a = fc1b[c];
#pragma unroll 8
    for (int k = 0; k < 64; k++) a = fmaf(p[k], fc1w[k * 64 + c], a);
    q[c] = fmaxf(a, 0.f);
    __syncthreads();
    if (c < NCLS) {
        float o = fc2b[c];
#pragma unroll 8
        for (int k = 0; k < 64; k++) o = fmaf(q[k], fc2w[k * NCLS + c], o);
        out[g * NCLS + c] = o;
    }
}

// ================= launch =================
extern "C" void kernel_launch(void* const* d_in, const int* in_sizes, int n_in,
                              void* d_out, int out_size) {
    const float* x   = (const float*)d_in[0];
    const int* ei    = (const int*)d_in[1];
    const int* batch = (const int*)d_in[2];

    float *pH, *pXL, *pXR;
    cudaGetSymbolAddress((void**)&pH,  g_H);
    cudaGetSymbolAddress((void**)&pXL, g_XL);
    cudaGetSymbolAddress((void**)&pXR, g_XR);

    // CSR build (edge topology constant across layers)
    k_deg_zero<<<(Nn + 255) / 256, 256>>>();
    k_deg<<<(ETOT + 255) / 256, 256>>>(ei);
    k_scan<<<1, 1024>>>();
    k_fill<<<(ETOT + 255) / 256, 256>>>(ei);

    dim3 ggrid((Nn + 127) / 128, 2);

    for (int i = 0; i < 4; i++) {
        int base = 3 + 6 * i;
        const float* Wl  = (const float*)d_in[base + 0];
        const float* Wr  = (const float*)d_in[base + 1];
        const float* att = (const float*)d_in[base + 2];
        const float* b   = (const float*)d_in[base + 3];
        const float* gam = (const float*)d_in[base + 4];
        const float* bet = (const float*)d_in[base + 5];
        const float* A = (i == 0) ? x : pH;
        int K = (i == 0) ? INDIM : CCH;

        sgemm_mma<<<ggrid, 256>>>(A, Wl, pXL, Nn, K);
        sgemm_mma<<<ggrid, 256>>>(A, Wr, pXR, Nn, K);

        k_init_bn<<<1, 256>>>();
        k_edge<<<(Nn + 7) / 8, 256>>>(att, b, i < 3 ? 1 : 0);
        int Ctot = (i < 3) ? CCH : HIDC;
        k_bnstats<<<(Nn + RPB - 1) / RPB, 256>>>(Ctot);
        k_bnapply<<<(Nn * Ctot + 255) / 256, 256>>>(gam, bet, Ctot);
    }

    k_pool_init<<<(Gg * HIDC + 255) / 256, 256>>>();
    k_pool<<<(Nn * HIDC + 255) / 256, 256>>>(batch);
    k_head<<<Gg, 64>>>((const float*)d_in[27], (const float*)d_in[28],
                       (const float*)d_in[29], (const float*)d_in[30],
                       (float*)d_out);
}

// round 7
// speedup vs baseline: 2.5014x; 1.0689x over previous
#include <cuda_runtime.h>
#include <math.h>
#include <cstdint>

#define Nn     30000
#define Ee     300000
#define ETOT   330000
#define Gg     128
#define INDIM  128
#define HIDC   64
#define NHEAD  4
#define CCH    256
#define NCLS   10
#define EPSBN  1e-5f
#define SLOPE  0.2f
#define RPB    64

// ---------------- scratch ----------------
__device__ float g_H  [Nn * CCH];
__device__ float g_XL [Nn * CCH];
__device__ float g_XR [Nn * CCH];
__device__ int   g_deg [Nn];
__device__ int   g_offs[Nn + 1];
__device__ int   g_cur [Nn];
__device__ int   g_esrc[ETOT];
__device__ float g_bnsum[CCH];
__device__ float g_bnsq [CCH];
__device__ float g_pool[Gg * HIDC];
__device__ float g_cnt [Gg];

// ================= mma.sync tf32 helpers =================
__device__ __forceinline__ uint32_t smem_u32(const void* p) {
    uint32_t a;
    asm("{ .reg .u64 t; cvta.to.shared.u64 t, %1; cvt.u32.u64 %0, t; }" : "=r"(a) : "l"(p));
    return a;
}
__device__ __forceinline__ uint32_t f2tf(float f) {
    uint32_t r;
    asm("cvt.rna.tf32.f32 %0, %1;" : "=r"(r) : "f"(f));
    return r;
}
__device__ __forceinline__ void mma_tf32(float* d, const uint32_t* a, const uint32_t* b) {
    asm volatile(
        "mma.sync.aligned.m16n8k8.row.col.f32.tf32.tf32.f32 "
        "{%0,%1,%2,%3}, {%4,%5,%6,%7}, {%8,%9}, {%0,%1,%2,%3};"
        : "+f"(d[0]), "+f"(d[1]), "+f"(d[2]), "+f"(d[3])
        : "r"(a[0]), "r"(a[1]), "r"(a[2]), "r"(a[3]), "r"(b[0]), "r"(b[1]));
}

// ================= GEMM: C[M,256] = A[M,K] * B[K,256]  (3xTF32 split) =======
// 128x128 block tile, BK=32, 256 threads = 8 warps (2m x 4n), warp tile 64x32.
// 2-stage cp.async double-buffered pipeline, dynamic smem.
#define SA_ST 36     // (4*r0+c0) all-distinct mod 32 -> conflict-free A frags
#define SB_ST 136    // (8*c0+r0-ish) conflict-free B frags
#define STAGE_A (128 * SA_ST)   // 4608 floats
#define STAGE_B (32 * SB_ST)    // 4352 floats
#define GEMM_SMEM (2 * (STAGE_A + STAGE_B) * sizeof(float))   // 71680 B

__global__ void __launch_bounds__(256) sgemm_mma(const float* __restrict__ A,
                                                 const float* __restrict__ B,
                                                 float* __restrict__ C, int M, int K) {
    extern __shared__ float sm[];
    float* sAb[2] = { sm, sm + STAGE_A };
    float* sBb[2] = { sm + 2 * STAGE_A, sm + 2 * STAGE_A + STAGE_B };

    const int tid = threadIdx.x;
    const int lane = tid & 31, wid = tid >> 5;
    const int wm = wid & 1, wn = wid >> 1;
    const int bm = blockIdx.x * 128, n0 = blockIdx.y * 128;
    const int r0 = lane >> 2, c0 = lane & 3;

    float d[4][4][4];
#pragma unroll
    for (int mt = 0; mt < 4; mt++)
#pragma unroll
        for (int nt = 0; nt < 4; nt++)
#pragma unroll
            for (int q = 0; q < 4; q++) d[mt][nt][q] = 0.f;

    const int arow = tid >> 1, acol = (tid & 1) * 16;
    const int brow = tid >> 3, bcol = (tid & 7) * 16;
    const bool aok = (bm + arow) < M;
    const float* Arow = A + (size_t)(bm + (aok ? arow : 0)) * K;  // clamped base
    const int anb = aok ? 16 : 0;

    uint32_t saddr[2], sbddr[2];
    saddr[0] = smem_u32(sAb[0]); saddr[1] = smem_u32(sAb[1]);
    sbddr[0] = smem_u32(sBb[0]); sbddr[1] = smem_u32(sBb[1]);

    const int KC = K >> 5;

    // ---- tile loader (cp.async) ----
#define LOAD_TILE(k0, buf) do {                                                 \
        uint32_t _sa = saddr[buf], _sb = sbddr[buf];                            \
        _Pragma("unroll")                                                       \
        for (int i = 0; i < 4; i++) {                                           \
            uint32_t da = _sa + (uint32_t)(arow * SA_ST + acol + i * 4) * 4;    \
            const float* srcp = Arow + (k0) + acol + i * 4;                     \
            asm volatile("cp.async.cg.shared.global [%0], [%1], 16, %2;"        \
                         :: "r"(da), "l"(srcp), "r"(anb));                      \
        }                                                                       \
        _Pragma("unroll")                                                       \
        for (int i = 0; i < 4; i++) {                                           \
            uint32_t db = _sb + (uint32_t)(brow * SB_ST + bcol + i * 4) * 4;    \
            const float* srcp = B + (size_t)((k0) + brow) * CCH + n0 + bcol + i * 4; \
            asm volatile("cp.async.cg.shared.global [%0], [%1], 16;"            \
                         :: "r"(db), "l"(srcp));                                \
        }                                                                       \
        asm volatile("cp.async.commit_group;");                                 \
    } while (0)

    LOAD_TILE(0, 0);

    for (int c = 0; c < KC; c++) {
        const int buf = c & 1;
        if (c + 1 < KC) {
            LOAD_TILE((c + 1) << 5, (c + 1) & 1);
            asm volatile("cp.async.wait_group 1;" ::: "memory");
        } else {
            asm volatile("cp.async.wait_group 0;" ::: "memory");
        }
        __syncthreads();

        const float* sA = sAb[buf];
        const float* sB = sBb[buf];
#pragma unroll
        for (int ks = 0; ks < 4; ks++) {
            const int k = ks * 8;
            uint32_t ah[4][4], al[4][4], bh[4][2], bl[4][2];
#pragma unroll
            for (int mt = 0; mt < 4; mt++) {
                const int rm = wm * 64 + mt * 16;
                float f[4];
                f[0] = sA[(rm + r0) * SA_ST + k + c0];
                f[1] = sA[(rm + r0 + 8) * SA_ST + k + c0];
                f[2] = sA[(rm + r0) * SA_ST + k + c0 + 4];
                f[3] = sA[(rm + r0 + 8) * SA_ST + k + c0 + 4];
#pragma unroll
                for (int q = 0; q < 4; q++) {
                    uint32_t h = f2tf(f[q]);
                    ah[mt][q] = h;
                    al[mt][q] = f2tf(f[q] - __uint_as_float(h));
                }
            }
#pragma unroll
            for (int nt = 0; nt < 4; nt++) {
                const int cn = wn * 32 + nt * 8 + r0;
                float g[2];
                g[0] = sB[(k + c0) * SB_ST + cn];
                g[1] = sB[(k + 4 + c0) * SB_ST + cn];
#pragma unroll
                for (int q = 0; q < 2; q++) {
                    uint32_t h = f2tf(g[q]);
                    bh[nt][q] = h;
                    bl[nt][q] = f2tf(g[q] - __uint_as_float(h));
                }
            }
#pragma unroll
            for (int mt = 0; mt < 4; mt++)
#pragma unroll
                for (int nt = 0; nt < 4; nt++) {
                    mma_tf32(d[mt][nt], ah[mt], bh[nt]);
                    mma_tf32(d[mt][nt], ah[mt], bl[nt]);
                    mma_tf32(d[mt][nt], al[mt], bh[nt]);
                }
        }
        __syncthreads();
    }

    // epilogue
#pragma unroll
    for (int mt = 0; mt < 4; mt++) {
        const int row = bm + wm * 64 + mt * 16 + r0;
#pragma unroll
        for (int nt = 0; nt < 4; nt++) {
            const int col = n0 + wn * 32 + nt * 8 + c0 * 2;
            if (row < M)
                *(float2*)(C + (size_t)row * CCH + col) = make_float2(d[mt][nt][0], d[mt][nt][1]);
            if (row + 8 < M)
                *(float2*)(C + (size_t)(row + 8) * CCH + col) = make_float2(d[mt][nt][2], d[mt][nt][3]);
        }
    }
}

// ================= CSR build =================
__global__ void k_deg_zero() {
    int i = blockIdx.x * blockDim.x + threadIdx.x;
    if (i < Nn) g_deg[i] = 0;
}
__global__ void k_deg(const int* __restrict__ ei) {
    int i = blockIdx.x * blockDim.x + threadIdx.x;
    if (i >= ETOT) return;
    int dst = (i < Ee) ? ei[Ee + i] : i - Ee;
    atomicAdd(&g_deg[dst], 1);
}
__global__ void k_scan() {   // single block, 1024 threads, warp-shuffle scan
    __shared__ int wsum[32];
    __shared__ int carry;
    int tid = threadIdx.x, lane = tid & 31, w = tid >> 5;
    if (tid == 0) carry = 0;
    __syncthreads();
    for (int base = 0; base < Nn; base += 1024) {
        int i = base + tid;
        int v = (i < Nn) ? g_deg[i] : 0;
        int x = v;
#pragma unroll
        for (int st = 1; st < 32; st <<= 1) {
            int t = __shfl_up_sync(0xffffffffu, x, st);
            if (lane >= st) x += t;
        }
        if (lane == 31) wsum[w] = x;
        __syncthreads();
        if (w == 0) {
            int s = wsum[lane];
#pragma unroll
            for (int st = 1; st < 32; st <<= 1) {
                int t = __shfl_up_sync(0xffffffffu, s, st);
                if (lane >= st) s += t;
            }
            wsum[lane] = s;
        }
        __syncthreads();
        int incl = x + (w ? wsum[w - 1] : 0) + carry;
        if (i < Nn) { g_offs[i + 1] = incl; g_cur[i] = incl - v; }
        __syncthreads();
        if (tid == 1023) carry = incl;
        if (base == 0 && tid == 0) g_offs[0] = 0;
        __syncthreads();
    }
}
__global__ void k_fill(const int* __restrict__ ei) {
    int i = blockIdx.x * blockDim.x + threadIdx.x;
    if (i >= ETOT) return;
    int src, dst;
    if (i < Ee) { src = ei[i]; dst = ei[Ee + i]; }
    else        { src = i - Ee; dst = src; }
    int pos = atomicAdd(&g_cur[dst], 1);
    g_esrc[pos] = src;
}

// ================= fused edge phase: warp per dst, online softmax =================
__global__ void k_edge(const float* __restrict__ att, const float* __restrict__ b,
                       int concat) {
    int dst = (blockIdx.x * blockDim.x + threadIdx.x) >> 5;
    if (dst >= Nn) return;
    int lane = threadIdx.x & 31;
    int h = lane >> 3, j = lane & 7;
    int off = h * HIDC + j * 8;

    const float4* xr = (const float4*)(g_XR + (size_t)dst * CCH + off);
    const float4* at = (const float4*)(att + off);
    float4 r0 = xr[0], r1 = xr[1];
    float4 t0 = at[0], t1 = at[1];
    float r[8] = {r0.x, r0.y, r0.z, r0.w, r1.x, r1.y, r1.z, r1.w};
    float t[8] = {t0.x, t0.y, t0.z, t0.w, t1.x, t1.y, t1.z, t1.w};

    float acc[8] = {0.f, 0.f, 0.f, 0.f, 0.f, 0.f, 0.f, 0.f};
    float m = -3.0e38f;
    float s = 0.f;

    int beg = g_offs[dst], end = g_offs[dst + 1];
    for (int p = beg; p < end; p++) {
        int src = g_esrc[p];
        const float4* xl = (const float4*)(g_XL + (size_t)src * CCH + off);
        float4 a0 = xl[0], a1 = xl[1];
        float a[8] = {a0.x, a0.y, a0.z, a0.w, a1.x, a1.y, a1.z, a1.w};
        float sc = 0.f;
#pragma unroll
        for (int k = 0; k < 8; k++) {
            float z = a[k] + r[k];
            z = z > 0.f ? z : SLOPE * z;
            sc = fmaf(t[k], z, sc);
        }
        sc += __shfl_xor_sync(0xffffffffu, sc, 1);
        sc += __shfl_xor_sync(0xffffffffu, sc, 2);
        sc += __shfl_xor_sync(0xffffffffu, sc, 4);
        if (sc > m) {
            float scale = expf(m - sc);   // first edge: 0
            m = sc;
            s = fmaf(s, scale, 1.f);
#pragma unroll
            for (int k = 0; k < 8; k++) acc[k] = fmaf(acc[k], scale, a[k]);
        } else {
            float pe = expf(sc - m);
            s += pe;
#pragma unroll
            for (int k = 0; k < 8; k++) acc[k] = fmaf(pe, a[k], acc[k]);
        }
    }
    float inv = 1.f / s;
    if (concat) {
        float* o = g_H + (size_t)dst * CCH + off;
#pragma unroll
        for (int k = 0; k < 8; k++) o[k] = fmaf(acc[k], inv, b[off + k]);
    } else {
        float v[8];
#pragma unroll
        for (int k = 0; k < 8; k++) {
            v[k] = acc[k] * inv;
            v[k] += __shfl_xor_sync(0xffffffffu, v[k], 8);
            v[k] += __shfl_xor_sync(0xffffffffu, v[k], 16);
        }
        if (h == 0) {
            float* o = g_H + (size_t)dst * HIDC + j * 8;
#pragma unroll
            for (int k = 0; k < 8; k++) o[k] = fmaf(0.25f, v[k], b[j * 8 + k]);
        }
    }
}

// ================= BN =================
__global__ void k_init_bn() {
    int i = threadIdx.x;
    g_bnsum[i] = 0.f;
    g_bnsq[i] = 0.f;
}
__global__ void k_bnstats(int Ctot) {
    int tid = threadIdx.x;                 // 256
    int c = tid % Ctot, sub = tid / Ctot, nsub = 256 / Ctot;
    int r0 = blockIdx.x * RPB;
    int rend = min(r0 + RPB, Nn);
    float s = 0.f, s2 = 0.f;
    for (int r = r0 + sub; r < rend; r += nsub) {
        float v = g_H[(size_t)r * Ctot + c];
        s += v;
        s2 += v * v;
    }
    atomicAdd(&g_bnsum[c], s);
    atomicAdd(&g_bnsq[c], s2);
}
__global__ void k_bnapply(const float* __restrict__ gam, const float* __restrict__ bet,
                          int Ctot) {
    int i = blockIdx.x * blockDim.x + threadIdx.x;
    if (i >= Nn * Ctot) return;
    int c = i % Ctot;
    float mu = g_bnsum[c] * (1.f / Nn);
    float var = g_bnsq[c] * (1.f / Nn) - mu * mu;
    float v = gam[c] * (g_H[i] - mu) * rsqrtf(var + EPSBN) + bet[c];
    g_H[i] = v > 0.f ? v : expm1f(v);
}

// ================= pooling + head =================
__global__ void k_pool_init() {
    int i = blockIdx.x * blockDim.x + threadIdx.x;
    if (i < Gg * HIDC) g_pool[i] = 0.f;
    if (i < Gg) g_cnt[i] = 0.f;
}
__global__ void k_pool(const int* __restrict__ batch) {
    int i = blockIdx.x * blockDim.x + threadIdx.x;
    if (i >= Nn * HIDC) return;
    int n = i >> 6, c = i & 63;
    int g = batch[n];
    atomicAdd(&g_pool[g * HIDC + c], g_H[i]);
    if (c == 0) atomicAdd(&g_cnt[g], 1.f);
}
__global__ void k_head(const float* __restrict__ fc1w, const float* __restrict__ fc1b,
                       const float* __restrict__ fc2w, const float* __restrict__ fc2b,
                       float* __restrict__ out) {
    __shared__ float p[64], q[64];
    int g = blockIdx.x, c = threadIdx.x;
    float cnt = fmaxf(g_cnt[g], 1.f);
    p[c] = g_pool[g * HIDC + c] / cnt;
    __syncthreads();
    float a = fc1b[c];
#pragma unroll 8
    for (int k = 0; k < 64; k++) a = fmaf(p[k], fc1w[k * 64 + c], a);
    q[c] = fmaxf(a, 0.f);
    __syncthreads();
    if (c < NCLS) {
        float o = fc2b[c];
#pragma unroll 8
        for (int k = 0; k < 64; k++) o = fmaf(q[k], fc2w[k * NCLS + c], o);
        out[g * NCLS + c] = o;
    }
}

// ================= launch =================
extern "C" void kernel_launch(void* const* d_in, const int* in_sizes, int n_in,
                              void* d_out, int out_size) {
    const float* x   = (const float*)d_in[0];
    const int* ei    = (const int*)d_in[1];
    const int* batch = (const int*)d_in[2];

    float *pH, *pXL, *pXR;
    cudaGetSymbolAddress((void**)&pH,  g_H);
    cudaGetSymbolAddress((void**)&pXL, g_XL);
    cudaGetSymbolAddress((void**)&pXR, g_XR);

    cudaFuncSetAttribute(sgemm_mma, cudaFuncAttributeMaxDynamicSharedMemorySize,
                         (int)GEMM_SMEM);

    // CSR build (edge topology constant across layers)
    k_deg_zero<<<(Nn + 255) / 256, 256>>>();
    k_deg<<<(ETOT + 255) / 256, 256>>>(ei);
    k_scan<<<1, 1024>>>();
    k_fill<<<(ETOT + 255) / 256, 256>>>(ei);

    dim3 ggrid((Nn + 127) / 128, 2);

    for (int i = 0; i < 4; i++) {
        int base = 3 + 6 * i;
        const float* Wl  = (const float*)d_in[base + 0];
        const float* Wr  = (const float*)d_in[base + 1];
        const float* att = (const float*)d_in[base + 2];
        const float* b   = (const float*)d_in[base + 3];
        const float* gam = (const float*)d_in[base + 4];
        const float* bet = (const float*)d_in[base + 5];
        const float* A = (i == 0) ? x : pH;
        int K = (i == 0) ? INDIM : CCH;

        sgemm_mma<<<ggrid, 256, GEMM_SMEM>>>(A, Wl, pXL, Nn, K);
        sgemm_mma<<<ggrid, 256, GEMM_SMEM>>>(A, Wr, pXR, Nn, K);

        k_init_bn<<<1, 256>>>();
        k_edge<<<(Nn + 7) / 8, 256>>>(att, b, i < 3 ? 1 : 0);
        int Ctot = (i < 3) ? CCH : HIDC;
        k_bnstats<<<(Nn + RPB - 1) / RPB, 256>>>(Ctot);
        k_bnapply<<<(Nn * Ctot + 255) / 256, 256>>>(gam, bet, Ctot);
    }

    k_pool_init<<<(Gg * HIDC + 255) / 256, 256>>>();
    k_pool<<<(Nn * HIDC + 255) / 256, 256>>>(batch);
    k_head<<<Gg, 64>>>((const float*)d_in[27], (const float*)d_in[28],
                       (const float*)d_in[29], (const float*)d_in[30],
                       (float*)d_out);
}